// round 16
// baseline (speedup 1.0000x reference)
#include <cuda_runtime.h>
#include <cuda_fp16.h>

#define N_NODES 50000
#define N_EDGES 800000
#define HID 64
#define CAP_LOG2 6                                 // 64 slots per node
#define EPAIR_BLOCKS ((N_EDGES / 2 + 255) / 256)   // 1563
#define AB1_NPW 8
#define AB1_BLOCKS ((N_NODES + 8 * AB1_NPW - 1) / (8 * AB1_NPW))  // 782

// ---- scratch (static device globals; zero-initialized at load) ----
__device__ int    g_deg[N_NODES];                  // re-zeroed by final gather
__device__ int    g_srcidx[N_NODES << CAP_LOG2];   // bucketed adjacency (12.8 MB)
__device__ float  g_A[N_NODES * HID];
__device__ __half g_Bh[N_NODES * HID];             // B table in fp16
__device__ __half g_Hh[N_NODES * HID];             // H in fp16 (layer-1 output)

typedef unsigned long long ull;

// ---- packed f32x2 helpers (identical .rn rounding to scalar fp32) ----
__device__ __forceinline__ ull pack2(float x, float y) {
    ull r;
    asm("mov.b64 %0, {%1, %2};" : "=l"(r) : "f"(x), "f"(y));
    return r;
}
__device__ __forceinline__ void unpack2(ull v, float& x, float& y) {
    asm("mov.b64 {%0, %1}, %2;" : "=f"(x), "=f"(y) : "l"(v));
}
__device__ __forceinline__ void fma2(ull& acc, ull a, ull b) {
    asm("fma.rn.f32x2 %0, %1, %2, %0;" : "+l"(acc) : "l"(a), "l"(b));
}

// ---------------- one-pass adjacency build (no scan, no second pass) --------
// slot = atomicAdd(deg[dst]); srcidx[dst*64 + slot] = src
// (g_deg is zero on entry: zero-init at load + re-zeroed by the final gather)
__global__ void k_count_fill(const int* __restrict__ ei) {
    int t = blockIdx.x * blockDim.x + threadIdx.x;
    int e = 2 * t;                       // N_EDGES is even
    if (e >= N_EDGES) return;
    int2 d = *(const int2*)&ei[N_EDGES + e];
    int2 s = *(const int2*)&ei[e];
    int r0 = atomicAdd(&g_deg[d.x], 1);
    g_srcidx[(d.x << CAP_LOG2) + r0] = s.x;
    int r1 = atomicAdd(&g_deg[d.y], 1);
    g_srcidx[(d.y << CAP_LOG2) + r1] = s.y;
}

// ---------------- layer-1 node pre-GEMMs: A = x@(Wtop-Wbot)+b, B = x@Wbot ----
// Weights live entirely in registers; zero LDS. (proven R12 winner)
__global__ void __launch_bounds__(256) k_nodeAB1(const float* __restrict__ x,
                                                 const float* __restrict__ w1a,
                                                 const float* __restrict__ b1a) {
    int warp = threadIdx.x >> 5, lane = threadIdx.x & 31;
    ull wd[16], wb[16];
#pragma unroll
    for (int k = 0; k < 16; k++) {
        float2 top = *(const float2*)&w1a[k * 64 + 2 * lane];
        float2 bot = *(const float2*)&w1a[(16 + k) * 64 + 2 * lane];
        wd[k] = pack2(top.x - bot.x, top.y - bot.y);
        wb[k] = pack2(bot.x, bot.y);
    }
    float2 bias = *(const float2*)&b1a[2 * lane];
    ull binit = pack2(bias.x, bias.y);

    int nbase = (blockIdx.x * 8 + warp) * AB1_NPW;
    float xv[AB1_NPW];
#pragma unroll
    for (int ni = 0; ni < AB1_NPW; ni++) {
        int node = nbase + ni;
        xv[ni] = (node < N_NODES && lane < 16) ? x[node * 16 + lane] : 0.f;
    }
#pragma unroll
    for (int ni = 0; ni < AB1_NPW; ni++) {
        int node = nbase + ni;
        if (node >= N_NODES) break;
        ull A = binit, C = 0ULL;
#pragma unroll
        for (int k = 0; k < 16; k++) {
            float xk = __shfl_sync(0xffffffffu, xv[ni], k);
            ull x2 = pack2(xk, xk);
            fma2(A, x2, wd[k]);
            fma2(C, x2, wb[k]);
        }
        float ax, ay, cx, cy;
        unpack2(A, ax, ay);
        unpack2(C, cx, cy);
        *(float2*)&g_A[node * 64 + lane * 2] = make_float2(ax, ay);
        ((__half2*)g_Bh)[node * 32 + lane] = __floats2half2_rn(cx, cy);
    }
}

// ---------------- edge gather + post-GEMM (both layers; FINAL fuses projection)
// per node i: acc = mean_e relu(A[i] + B[src_e]); h = relu(acc@Wp + bp)
// Bucketed adjacency: edges of node i live at [i<<6, i<<6 + deg).
// FINAL==1 additionally re-zeroes g_deg[node] after reading (invariant).
template <int FINAL>
__global__ void __launch_bounds__(256) k_gather_t(const float* __restrict__ Wp,
                                                  const float* __restrict__ bp,
                                                  const float* __restrict__ wl,
                                                  const float* __restrict__ bl,
                                                  float* __restrict__ out) {
    __shared__ float wsh[64 * 64];
    __shared__ float bshm[64];
    __shared__ float accsh[8][64][4];   // [warp][channel][node-in-warp]
    int tid = threadIdx.x;
    for (int i = tid; i < 64 * 64; i += 256) wsh[i] = Wp[i];
    if (tid < 64) bshm[tid] = bp[tid];
    __syncthreads();
    int warp = tid >> 5, lane = tid & 31;
    int nbase = (blockIdx.x * 8 + warp) * 4;
    const __half2* __restrict__ Bh2 = (const __half2*)g_Bh;

    int dg[4];
#pragma unroll
    for (int ni = 0; ni < 4; ni++) {
        int node = nbase + ni;
        float acc0 = 0.f, acc1 = 0.f;
        int deg = 0;
        if (node < N_NODES) {
            deg = g_deg[node];
            if (FINAL == 1 && lane == 0) g_deg[node] = 0;  // restore invariant
            int e0 = node << CAP_LOG2, e1 = e0 + deg;
            float2 a = *(const float2*)&g_A[node * 64 + lane * 2];
            int e = e0;
            for (; e + 8 <= e1; e += 8) {
                int s[8];
#pragma unroll
                for (int j = 0; j < 8; j++) s[j] = g_srcidx[e + j];
                float2 b[8];
#pragma unroll
                for (int j = 0; j < 8; j++) b[j] = __half22float2(Bh2[s[j] * 32 + lane]);
#pragma unroll
                for (int j = 0; j < 8; j++) {
                    acc0 += fmaxf(a.x + b[j].x, 0.f);
                    acc1 += fmaxf(a.y + b[j].y, 0.f);
                }
            }
            if (e + 4 <= e1) {
                int s[4];
#pragma unroll
                for (int j = 0; j < 4; j++) s[j] = g_srcidx[e + j];
                float2 b[4];
#pragma unroll
                for (int j = 0; j < 4; j++) b[j] = __half22float2(Bh2[s[j] * 32 + lane]);
#pragma unroll
                for (int j = 0; j < 4; j++) {
                    acc0 += fmaxf(a.x + b[j].x, 0.f);
                    acc1 += fmaxf(a.y + b[j].y, 0.f);
                }
                e += 4;
            }
            for (; e < e1; e++) {
                int s = g_srcidx[e];
                float2 bb = __half22float2(Bh2[s * 32 + lane]);
                acc0 += fmaxf(a.x + bb.x, 0.f);
                acc1 += fmaxf(a.y + bb.y, 0.f);
            }
            if (deg > 0) {
                float inv = 1.0f / (float)deg;
                acc0 *= inv;
                acc1 *= inv;
            }
        }
        dg[ni] = deg;
        accsh[warp][2 * lane][ni] = acc0;
        accsh[warp][2 * lane + 1][ni] = acc1;
    }
    __syncwarp();

    // fused 4-node epilogue GEMM in packed f32x2
    ull accA[4];
    {
        ull binit = pack2(bshm[2 * lane], bshm[2 * lane + 1]);
#pragma unroll
        for (int ni = 0; ni < 4; ni++) accA[ni] = binit;
    }
#pragma unroll 8
    for (int k = 0; k < 64; k++) {
        float4 av = *(const float4*)&accsh[warp][k][0];
        ull w2 = *(const ull*)&wsh[k * 64 + 2 * lane];
        fma2(accA[0], pack2(av.x, av.x), w2);
        fma2(accA[1], pack2(av.y, av.y), w2);
        fma2(accA[2], pack2(av.z, av.z), w2);
        fma2(accA[3], pack2(av.w, av.w), w2);
    }

    if (FINAL == 0) {
#pragma unroll
        for (int ni = 0; ni < 4; ni++) {
            int node = nbase + ni;
            if (node >= N_NODES) break;
            float o0, o1;
            unpack2(accA[ni], o0, o1);
            if (dg[ni] > 0) { o0 = fmaxf(o0, 0.f); o1 = fmaxf(o1, 0.f); }
            else            { o0 = 0.f; o1 = 0.f; }
            ((__half2*)g_Hh)[node * 32 + lane] = __floats2half2_rn(o0, o1);
        }
    } else {
        float4 w = *(const float4*)&wl[lane * 4];
        float bl0 = bl[0], bl1 = bl[1];
#pragma unroll
        for (int ni = 0; ni < 4; ni++) {
            int node = nbase + ni;
            if (node >= N_NODES) break;
            float o0, o1;
            unpack2(accA[ni], o0, o1);
            if (dg[ni] > 0) { o0 = fmaxf(o0, 0.f); o1 = fmaxf(o1, 0.f); }
            else            { o0 = 0.f; o1 = 0.f; }
            float p0 = o0 * w.x + o1 * w.z;
            float p1 = o0 * w.y + o1 * w.w;
#pragma unroll
            for (int ofs = 16; ofs > 0; ofs >>= 1) {
                p0 += __shfl_xor_sync(0xffffffffu, p0, ofs);
                p1 += __shfl_xor_sync(0xffffffffu, p1, ofs);
            }
            if (lane == 0) {
                out[node * 2 + 0] = p0 + bl0;
                out[node * 2 + 1] = p1 + bl1;
            }
        }
    }
}

// ---------------- layer-2 node pre-GEMMs from H(fp16): 8 nodes/warp, f32x2 ---
__global__ void __launch_bounds__(256) k_nodeAB2(const float* __restrict__ w2a,
                                                 const float* __restrict__ b2a) {
    __shared__ float wdb[64 * 32 * 4];
    __shared__ float bshm[64];
    __shared__ float hsh[8][64 * 8];
    int tid = threadIdx.x;
    for (int idx = tid; idx < 64 * 64; idx += 256) {
        int k = idx >> 6, col = idx & 63;
        float top = w2a[idx];
        float bot = w2a[64 * 64 + idx];
        int ln = col >> 1, comp = col & 1;
        wdb[(k * 32 + ln) * 4 + comp]     = top - bot;
        wdb[(k * 32 + ln) * 4 + 2 + comp] = bot;
    }
    if (tid < 64) bshm[tid] = b2a[tid];
    __syncthreads();
    int warp = tid >> 5, lane = tid & 31;
    int nbase = (blockIdx.x * 8 + warp) * 8;
    const __half2* __restrict__ Hh2 = (const __half2*)g_Hh;

#pragma unroll
    for (int ni = 0; ni < 8; ni++) {
        int node = nbase + ni;
        float2 h = (node < N_NODES) ? __half22float2(Hh2[node * 32 + lane])
                                    : make_float2(0.f, 0.f);
        hsh[warp][(2 * lane) * 8 + ni]     = h.x;
        hsh[warp][(2 * lane + 1) * 8 + ni] = h.y;
    }
    __syncwarp();

    ull A[8], C[8];
    ull binit = pack2(bshm[2 * lane], bshm[2 * lane + 1]);
#pragma unroll
    for (int ni = 0; ni < 8; ni++) { A[ni] = binit; C[ni] = 0ULL; }

#pragma unroll 4
    for (int k = 0; k < 64; k++) {
        float4 h03 = *(const float4*)&hsh[warp][k * 8];
        float4 h47 = *(const float4*)&hsh[warp][k * 8 + 4];
        const ull* wp = (const ull*)&wdb[(k * 32 + lane) * 4];
        ull wd2 = wp[0], wb2 = wp[1];
        ull hh;
        hh = pack2(h03.x, h03.x); fma2(A[0], hh, wd2); fma2(C[0], hh, wb2);
        hh = pack2(h03.y, h03.y); fma2(A[1], hh, wd2); fma2(C[1], hh, wb2);
        hh = pack2(h03.z, h03.z); fma2(A[2], hh, wd2); fma2(C[2], hh, wb2);
        hh = pack2(h03.w, h03.w); fma2(A[3], hh, wd2); fma2(C[3], hh, wb2);
        hh = pack2(h47.x, h47.x); fma2(A[4], hh, wd2); fma2(C[4], hh, wb2);
        hh = pack2(h47.y, h47.y); fma2(A[5], hh, wd2); fma2(C[5], hh, wb2);
        hh = pack2(h47.z, h47.z); fma2(A[6], hh, wd2); fma2(C[6], hh, wb2);
        hh = pack2(h47.w, h47.w); fma2(A[7], hh, wd2); fma2(C[7], hh, wb2);
    }
#pragma unroll
    for (int ni = 0; ni < 8; ni++) {
        int node = nbase + ni;
        if (node >= N_NODES) break;
        float ax, ay, cx, cy;
        unpack2(A[ni], ax, ay);
        unpack2(C[ni], cx, cy);
        *(float2*)&g_A[node * 64 + lane * 2] = make_float2(ax, ay);
        ((__half2*)g_Bh)[node * 32 + lane] = __floats2half2_rn(cx, cy);
    }
}

extern "C" void kernel_launch(void* const* d_in, const int* in_sizes, int n_in,
                              void* d_out, int out_size) {
    const float* x   = (const float*)d_in[0];
    const int*   ei  = (const int*)d_in[1];   // int32 (JAX default x64 disabled)
    const float* w1a = (const float*)d_in[2];
    const float* b1a = (const float*)d_in[3];
    const float* w1b = (const float*)d_in[4];
    const float* b1b = (const float*)d_in[5];
    const float* w2a = (const float*)d_in[6];
    const float* b2a = (const float*)d_in[7];
    const float* w2b = (const float*)d_in[8];
    const float* b2b = (const float*)d_in[9];
    const float* wl  = (const float*)d_in[10];
    const float* bl  = (const float*)d_in[11];
    float* out = (float*)d_out;

    int gather_blocks = (N_NODES + 31) / 32;   // 8 warps x 4 nodes
    int ab2_blocks    = (N_NODES + 63) / 64;   // 8 warps x 8 nodes

    // one-pass bucketed adjacency build (replaces count+scan+fill)
    k_count_fill<<<EPAIR_BLOCKS, 256>>>(ei);

    // layer 1
    k_nodeAB1<<<AB1_BLOCKS, 256>>>(x, w1a, b1a);
    k_gather_t<0><<<gather_blocks, 256>>>(w1b, b1b, wl, bl, out);

    // layer 2 (+ fused final projection; re-zeroes g_deg)
    k_nodeAB2<<<ab2_blocks, 256>>>(w2a, b2a);
    k_gather_t<1><<<gather_blocks, 256>>>(w2b, b2b, wl, bl, out);
}

// round 17
// speedup vs baseline: 1.3863x; 1.3863x over previous
#include <cuda_runtime.h>
#include <cuda_fp16.h>

#define N_NODES 50000
#define N_EDGES 800000
#define HID 64
#define SCAN_BLOCKS ((N_NODES + 255) / 256)       // 196
#define EPAIR_BLOCKS ((N_EDGES / 2 + 255) / 256)  // 1563
#define AB1_NPW 8
#define AB1_BLOCKS ((N_NODES + 8 * AB1_NPW - 1) / (8 * AB1_NPW))  // 782
#define AB2_BLOCKS ((N_NODES + 127) / 128)        // 391 (8 warps x 16 nodes)

// ---- scratch (static device globals; zero-initialized at load) ----
__device__ int    g_deg[N_NODES];       // re-zeroed by k_scan23 each call
__device__ int    g_off[N_NODES + 1];
__device__ int    g_rank[N_EDGES];      // packed: (rank << 16) | dst
__device__ int    g_bsum[256];
__device__ int    g_srcidx[N_EDGES];
__device__ float  g_A[N_NODES * HID];
__device__ __half g_Bh[N_NODES * HID];  // B table in fp16
__device__ __half g_Hh[N_NODES * HID];  // H in fp16 (layer-1 output)

typedef unsigned long long ull;

// ---- packed f32x2 helpers (identical .rn rounding to scalar fp32) ----
__device__ __forceinline__ ull pack2(float x, float y) {
    ull r;
    asm("mov.b64 %0, {%1, %2};" : "=l"(r) : "f"(x), "f"(y));
    return r;
}
__device__ __forceinline__ void unpack2(ull v, float& x, float& y) {
    asm("mov.b64 {%0, %1}, %2;" : "=f"(x), "=f"(y) : "l"(v));
}
__device__ __forceinline__ void fma2(ull& acc, ull a, ull b) {
    asm("fma.rn.f32x2 %0, %1, %2, %0;" : "+l"(acc) : "l"(a), "l"(b));
}

// ---- tensor-core helpers ----
__device__ __forceinline__ unsigned smem_u32(const void* p) {
    unsigned r;
    asm("{ .reg .u64 t; cvta.to.shared.u64 t, %1; cvt.u32.u64 %0, t; }"
        : "=r"(r) : "l"(p));
    return r;
}
__device__ __forceinline__ void ldmA4(unsigned& a0, unsigned& a1, unsigned& a2,
                                      unsigned& a3, unsigned addr) {
    asm volatile("ldmatrix.sync.aligned.m8n8.x4.shared.b16 {%0,%1,%2,%3}, [%4];"
                 : "=r"(a0), "=r"(a1), "=r"(a2), "=r"(a3) : "r"(addr));
}
__device__ __forceinline__ void ldmB2t(unsigned& b0, unsigned& b1, unsigned addr) {
    asm volatile("ldmatrix.sync.aligned.m8n8.x2.trans.shared.b16 {%0,%1}, [%2];"
                 : "=r"(b0), "=r"(b1) : "r"(addr));
}
__device__ __forceinline__ void mma16816(float& d0, float& d1, float& d2, float& d3,
                                         unsigned a0, unsigned a1, unsigned a2,
                                         unsigned a3, unsigned b0, unsigned b1) {
    asm volatile(
        "mma.sync.aligned.m16n8k16.row.col.f32.f16.f16.f32 "
        "{%0,%1,%2,%3}, {%4,%5,%6,%7}, {%8,%9}, {%0,%1,%2,%3};"
        : "+f"(d0), "+f"(d1), "+f"(d2), "+f"(d3)
        : "r"(a0), "r"(a1), "r"(a2), "r"(a3), "r"(b0), "r"(b1));
}

// ---------------- CSR build (R12-proven) ----------------
__global__ void k_count(const int* __restrict__ ei) {
    int t = blockIdx.x * blockDim.x + threadIdx.x;
    int e = 2 * t;
    if (e + 1 < N_EDGES) {
        int2 d = *(const int2*)&ei[N_EDGES + e];
        int r0 = atomicAdd(&g_deg[d.x], 1);
        int r1 = atomicAdd(&g_deg[d.y], 1);
        *(int2*)&g_rank[e] = make_int2((r0 << 16) | d.x, (r1 << 16) | d.y);
    } else if (e < N_EDGES) {
        int dst = ei[N_EDGES + e];
        int r = atomicAdd(&g_deg[dst], 1);
        g_rank[e] = (r << 16) | dst;
    }
}

__global__ void k_scan1() {
    __shared__ int sh[256];
    int tid = threadIdx.x;
    int i = blockIdx.x * 256 + tid;
    int v = (i < N_NODES) ? g_deg[i] : 0;
    sh[tid] = v;
    __syncthreads();
#pragma unroll
    for (int ofs = 1; ofs < 256; ofs <<= 1) {
        int t = (tid >= ofs) ? sh[tid - ofs] : 0;
        __syncthreads();
        sh[tid] += t;
        __syncthreads();
    }
    if (i < N_NODES) g_off[i] = sh[tid] - v;
    if (tid == 255) g_bsum[blockIdx.x] = sh[255];
}

__global__ void k_scan23() {
    __shared__ int sh[256];
    int tid = threadIdx.x;
    int v = (tid < SCAN_BLOCKS) ? g_bsum[tid] : 0;
    sh[tid] = v;
    __syncthreads();
#pragma unroll
    for (int ofs = 1; ofs < 256; ofs <<= 1) {
        int t = (tid >= ofs) ? sh[tid - ofs] : 0;
        __syncthreads();
        sh[tid] += t;
        __syncthreads();
    }
    int prefix = (blockIdx.x == 0) ? 0 : sh[blockIdx.x - 1];
    int i = blockIdx.x * 256 + tid;
    if (i < N_NODES) {
        g_off[i] += prefix;
        g_deg[i] = 0;
    }
    if (blockIdx.x == 0 && tid == 0) g_off[N_NODES] = sh[255];
}

__global__ void k_fill(const int* __restrict__ ei) {
    int t = blockIdx.x * blockDim.x + threadIdx.x;
    int e = 2 * t;
    if (e + 1 < N_EDGES) {
        int2 r = *(const int2*)&g_rank[e];
        int2 s = *(const int2*)&ei[e];
        g_srcidx[g_off[r.x & 0xFFFF] + (r.x >> 16)] = s.x;
        g_srcidx[g_off[r.y & 0xFFFF] + (r.y >> 16)] = s.y;
    } else if (e < N_EDGES) {
        int r = g_rank[e];
        g_srcidx[g_off[r & 0xFFFF] + (r >> 16)] = ei[e];
    }
}

// ---------------- layer-1 node pre-GEMMs (R12-proven, weights in regs) ------
__global__ void __launch_bounds__(256) k_nodeAB1(const float* __restrict__ x,
                                                 const float* __restrict__ w1a,
                                                 const float* __restrict__ b1a) {
    int warp = threadIdx.x >> 5, lane = threadIdx.x & 31;
    ull wd[16], wb[16];
#pragma unroll
    for (int k = 0; k < 16; k++) {
        float2 top = *(const float2*)&w1a[k * 64 + 2 * lane];
        float2 bot = *(const float2*)&w1a[(16 + k) * 64 + 2 * lane];
        wd[k] = pack2(top.x - bot.x, top.y - bot.y);
        wb[k] = pack2(bot.x, bot.y);
    }
    float2 bias = *(const float2*)&b1a[2 * lane];
    ull binit = pack2(bias.x, bias.y);

    int nbase = (blockIdx.x * 8 + warp) * AB1_NPW;
    float xv[AB1_NPW];
#pragma unroll
    for (int ni = 0; ni < AB1_NPW; ni++) {
        int node = nbase + ni;
        xv[ni] = (node < N_NODES && lane < 16) ? x[node * 16 + lane] : 0.f;
    }
#pragma unroll
    for (int ni = 0; ni < AB1_NPW; ni++) {
        int node = nbase + ni;
        if (node >= N_NODES) break;
        ull A = binit, C = 0ULL;
#pragma unroll
        for (int k = 0; k < 16; k++) {
            float xk = __shfl_sync(0xffffffffu, xv[ni], k);
            ull x2 = pack2(xk, xk);
            fma2(A, x2, wd[k]);
            fma2(C, x2, wb[k]);
        }
        float ax, ay, cx, cy;
        unpack2(A, ax, ay);
        unpack2(C, cx, cy);
        *(float2*)&g_A[node * 64 + lane * 2] = make_float2(ax, ay);
        ((__half2*)g_Bh)[node * 32 + lane] = __floats2half2_rn(cx, cy);
    }
}

// ---------------- edge gather + post-GEMM (R12-proven, byte-identical) ------
template <int FINAL>
__global__ void __launch_bounds__(256) k_gather_t(const float* __restrict__ Wp,
                                                  const float* __restrict__ bp,
                                                  const float* __restrict__ wl,
                                                  const float* __restrict__ bl,
                                                  float* __restrict__ out) {
    __shared__ float wsh[64 * 64];
    __shared__ float bshm[64];
    __shared__ float accsh[8][64][4];
    int tid = threadIdx.x;
    for (int i = tid; i < 64 * 64; i += 256) wsh[i] = Wp[i];
    if (tid < 64) bshm[tid] = bp[tid];
    __syncthreads();
    int warp = tid >> 5, lane = tid & 31;
    int nbase = (blockIdx.x * 8 + warp) * 4;
    const __half2* __restrict__ Bh2 = (const __half2*)g_Bh;

    int dg[4];
#pragma unroll
    for (int ni = 0; ni < 4; ni++) {
        int node = nbase + ni;
        float acc0 = 0.f, acc1 = 0.f;
        int deg = 0;
        if (node < N_NODES) {
            int e0 = g_off[node], e1 = g_off[node + 1];
            deg = e1 - e0;
            float2 a = *(const float2*)&g_A[node * 64 + lane * 2];
            int e = e0;
            for (; e + 8 <= e1; e += 8) {
                int s[8];
#pragma unroll
                for (int j = 0; j < 8; j++) s[j] = g_srcidx[e + j];
                float2 b[8];
#pragma unroll
                for (int j = 0; j < 8; j++) b[j] = __half22float2(Bh2[s[j] * 32 + lane]);
#pragma unroll
                for (int j = 0; j < 8; j++) {
                    acc0 += fmaxf(a.x + b[j].x, 0.f);
                    acc1 += fmaxf(a.y + b[j].y, 0.f);
                }
            }
            if (e + 4 <= e1) {
                int s[4];
#pragma unroll
                for (int j = 0; j < 4; j++) s[j] = g_srcidx[e + j];
                float2 b[4];
#pragma unroll
                for (int j = 0; j < 4; j++) b[j] = __half22float2(Bh2[s[j] * 32 + lane]);
#pragma unroll
                for (int j = 0; j < 4; j++) {
                    acc0 += fmaxf(a.x + b[j].x, 0.f);
                    acc1 += fmaxf(a.y + b[j].y, 0.f);
                }
                e += 4;
            }
            for (; e < e1; e++) {
                int s = g_srcidx[e];
                float2 bb = __half22float2(Bh2[s * 32 + lane]);
                acc0 += fmaxf(a.x + bb.x, 0.f);
                acc1 += fmaxf(a.y + bb.y, 0.f);
            }
            if (deg > 0) {
                float inv = 1.0f / (float)deg;
                acc0 *= inv;
                acc1 *= inv;
            }
        }
        dg[ni] = deg;
        accsh[warp][2 * lane][ni] = acc0;
        accsh[warp][2 * lane + 1][ni] = acc1;
    }
    __syncwarp();

    ull accA[4];
    {
        ull binit = pack2(bshm[2 * lane], bshm[2 * lane + 1]);
#pragma unroll
        for (int ni = 0; ni < 4; ni++) accA[ni] = binit;
    }
#pragma unroll 8
    for (int k = 0; k < 64; k++) {
        float4 av = *(const float4*)&accsh[warp][k][0];
        ull w2 = *(const ull*)&wsh[k * 64 + 2 * lane];
        fma2(accA[0], pack2(av.x, av.x), w2);
        fma2(accA[1], pack2(av.y, av.y), w2);
        fma2(accA[2], pack2(av.z, av.z), w2);
        fma2(accA[3], pack2(av.w, av.w), w2);
    }

    if (FINAL == 0) {
#pragma unroll
        for (int ni = 0; ni < 4; ni++) {
            int node = nbase + ni;
            if (node >= N_NODES) break;
            float o0, o1;
            unpack2(accA[ni], o0, o1);
            if (dg[ni] > 0) { o0 = fmaxf(o0, 0.f); o1 = fmaxf(o1, 0.f); }
            else            { o0 = 0.f; o1 = 0.f; }
            ((__half2*)g_Hh)[node * 32 + lane] = __floats2half2_rn(o0, o1);
        }
    } else {
        float4 w = *(const float4*)&wl[lane * 4];
        float bl0 = bl[0], bl1 = bl[1];
#pragma unroll
        for (int ni = 0; ni < 4; ni++) {
            int node = nbase + ni;
            if (node >= N_NODES) break;
            float o0, o1;
            unpack2(accA[ni], o0, o1);
            if (dg[ni] > 0) { o0 = fmaxf(o0, 0.f); o1 = fmaxf(o1, 0.f); }
            else            { o0 = 0.f; o1 = 0.f; }
            float p0 = o0 * w.x + o1 * w.z;
            float p1 = o0 * w.y + o1 * w.w;
#pragma unroll
            for (int ofs = 16; ofs > 0; ofs >>= 1) {
                p0 += __shfl_xor_sync(0xffffffffu, p0, ofs);
                p1 += __shfl_xor_sync(0xffffffffu, p1, ofs);
            }
            if (lane == 0) {
                out[node * 2 + 0] = p0 + bl0;
                out[node * 2 + 1] = p1 + bl1;
            }
        }
    }
}

// ---------------- layer-2 node pre-GEMMs via tensor cores -------------------
// D[node][0:128] = H[node][0:64] @ [wd | wb]  (wd = W2a_top - W2a_bot, wb = bot)
// A2 = D[:, 0:64] + b2a   ->  g_A (fp32)
// B2 = D[:, 64:128]       ->  g_Bh (fp16)
// mma.m16n8k16: per warp 16 nodes, 4 k-chunks x 16 n-tiles.
#define WH_PITCH 136   // halfs per row (64+64 data + 8 pad); 272B, 16B-mult
#define HS_PITCH 72    // halfs per row (64 data + 8 pad); 144B, 16B-mult
__global__ void __launch_bounds__(256) k_nodeAB2_mma(const float* __restrict__ w2a,
                                                     const float* __restrict__ b2a) {
    __shared__ __half Wh[64 * WH_PITCH];
    __shared__ __half Hs[8][16 * HS_PITCH];
    __shared__ float  bsh[64];
    int tid = threadIdx.x, warp = tid >> 5, lane = tid & 31;

    // weights fp32 -> fp16 combined [k][n] row-major (n<64: wd, n>=64: wb)
    for (int idx = tid; idx < 64 * 64; idx += 256) {
        int k = idx >> 6, n = idx & 63;
        float top = w2a[idx];
        float bot = w2a[64 * 64 + idx];
        Wh[k * WH_PITCH + n]      = __float2half_rn(top - bot);
        Wh[k * WH_PITCH + 64 + n] = __float2half_rn(bot);
    }
    if (tid < 64) bsh[tid] = b2a[tid];

    // per-warp H tile: 16 nodes x 64 halfs, 16B chunks (4 per lane)
    int nbase = (blockIdx.x * 8 + warp) * 16;
#pragma unroll
    for (int i = 0; i < 4; i++) {
        int chunk = i * 32 + lane;          // 0..127
        int r = chunk >> 3, seg = chunk & 7;
        int node = nbase + r;
        uint4 v = make_uint4(0, 0, 0, 0);
        if (node < N_NODES)
            v = *(const uint4*)&g_Hh[node * 64 + seg * 8];
        *(uint4*)&Hs[warp][r * HS_PITCH + seg * 8] = v;
    }
    __syncthreads();

    unsigned hbase = smem_u32(&Hs[warp][0]);
    unsigned wbase = smem_u32(&Wh[0]);

    float d[16][4];
#pragma unroll
    for (int nt = 0; nt < 16; nt++) {
        d[nt][0] = 0.f; d[nt][1] = 0.f; d[nt][2] = 0.f; d[nt][3] = 0.f;
    }

    int sub = lane & 7, q = lane >> 3;
#pragma unroll
    for (int kc = 0; kc < 4; kc++) {
        // A frag: 16x16 f16 at Hs[:, kc*16 .. +16]
        int arow = (q & 1) * 8 + sub;
        int acol = kc * 16 + (q >> 1) * 8;
        unsigned aaddr = hbase + (arow * HS_PITCH + acol) * 2;
        unsigned a0, a1, a2, a3;
        ldmA4(a0, a1, a2, a3, aaddr);

        // B frags: Wh[kc*16..+16][nt*8..+8], trans
        int brow = kc * 16 + (lane & 15);   // lanes 0-15 give rows; 16-31 mirrored
        unsigned baddr0 = wbase + brow * (WH_PITCH * 2);
#pragma unroll
        for (int nt = 0; nt < 16; nt++) {
            unsigned b0, b1;
            ldmB2t(b0, b1, baddr0 + nt * 16);   // 8 halfs = 16 bytes per tile col
            mma16816(d[nt][0], d[nt][1], d[nt][2], d[nt][3],
                     a0, a1, a2, a3, b0, b1);
        }
    }

    // epilogue: thread (g = lane>>2, tg = lane&3) holds rows g, g+8; cols 2tg,2tg+1
    int g = lane >> 2, tg = lane & 3;
    int n0 = nbase + g, n1 = nbase + g + 8;
#pragma unroll
    for (int nt = 0; nt < 16; nt++) {
        int c = nt * 8 + 2 * tg;
        if (c < 64) {
            float bx = bsh[c], by = bsh[c + 1];
            if (n0 < N_NODES)
                *(float2*)&g_A[n0 * 64 + c] = make_float2(d[nt][0] + bx, d[nt][1] + by);
            if (n1 < N_NODES)
                *(float2*)&g_A[n1 * 64 + c] = make_float2(d[nt][2] + bx, d[nt][3] + by);
        } else {
            int cc = c - 64;
            if (n0 < N_NODES)
                ((__half2*)g_Bh)[n0 * 32 + (cc >> 1)] = __floats2half2_rn(d[nt][0], d[nt][1]);
            if (n1 < N_NODES)
                ((__half2*)g_Bh)[n1 * 32 + (cc >> 1)] = __floats2half2_rn(d[nt][2], d[nt][3]);
        }
    }
}

extern "C" void kernel_launch(void* const* d_in, const int* in_sizes, int n_in,
                              void* d_out, int out_size) {
    const float* x   = (const float*)d_in[0];
    const int*   ei  = (const int*)d_in[1];   // int32 (JAX default x64 disabled)
    const float* w1a = (const float*)d_in[2];
    const float* b1a = (const float*)d_in[3];
    const float* w1b = (const float*)d_in[4];
    const float* b1b = (const float*)d_in[5];
    const float* w2a = (const float*)d_in[6];
    const float* b2a = (const float*)d_in[7];
    const float* w2b = (const float*)d_in[8];
    const float* b2b = (const float*)d_in[9];
    const float* wl  = (const float*)d_in[10];
    const float* bl  = (const float*)d_in[11];
    float* out = (float*)d_out;

    // CSR build: count(+packed rank) -> scan1 -> scan23(+re-zero deg) -> fill
    k_count<<<EPAIR_BLOCKS, 256>>>(ei);
    k_scan1<<<SCAN_BLOCKS, 256>>>();
    k_scan23<<<SCAN_BLOCKS, 256>>>();
    k_fill<<<EPAIR_BLOCKS, 256>>>(ei);

    int gather_blocks = (N_NODES + 31) / 32;   // 8 warps x 4 nodes

    // layer 1
    k_nodeAB1<<<AB1_BLOCKS, 256>>>(x, w1a, b1a);
    k_gather_t<0><<<gather_blocks, 256>>>(w1b, b1b, wl, bl, out);

    // layer 2 (+ fused final projection)
    k_nodeAB2_mma<<<AB2_BLOCKS, 256>>>(w2a, b2a);
    k_gather_t<1><<<gather_blocks, 256>>>(w2b, b2b, wl, bl, out);
}